// round 7
// baseline (speedup 1.0000x reference)
#include <cuda_runtime.h>
#include <math.h>

#define BS 8
#define F 16
#define NI 24
#define L 16384            // H*W
#define NGRP (L / 32)      // 512 pixel-groups per batch
#define IH 12              // instances per warp (instance half)
#define GPW 4              // groups per warp in k_sums

// ---------------- scratch (no allocations; zero-init; kernels restore zeros) ----------
__device__ float    g_sumsP[BS][NI][32];   // padded: one 128B line per (b,i)
__device__ float    g_counts[BS][NI];
__device__ float    g_means[BS][NI][F];
__device__ float    g_mm[BS][NI];
__device__ unsigned g_masks[BS][NGRP][NI];
__device__ float    g_varnum[BS];
__device__ float    g_varden[BS];
__device__ float    g_hinge[BS];
__device__ float    g_reg[BS];

// ================= K1: sums / counts / masks =================
// grid = (32, BS): blockIdx.x = blkb*2 + ih (blkb 0..15). Warp covers 4 groups x 12 inst.
__global__ void __launch_bounds__(256) k_sums(const float* __restrict__ inp,
                                              const int* __restrict__ tgt,
                                              const int* __restrict__ nobj) {
    const int b    = blockIdx.y;
    const int ih   = blockIdx.x & 1;
    const int blkb = blockIdx.x >> 1;             // 0..15
    const int tid  = threadIdx.x;
    const int warp = tid >> 5;
    const int lane = tid & 31;
    const int f    = lane & 15;
    const int half = lane >> 4;
    const int i0   = ih * IH;
    const int nb   = __ldg(nobj + b);
    int ni = nb - i0; ni = ni < 0 ? 0 : (ni > IH ? IH : ni);

    __shared__ float sh_w[8][IH][F];              // 6KB partials
    __shared__ float sh_c[8][IH];

    float acc[IH], ct[IH];
#pragma unroll
    for (int j = 0; j < IH; j++) { acc[j] = 0.f; ct[j] = 0.f; }

    if (ni > 0) {
        for (int q = 0; q < GPW; q++) {
            const int g  = (blkb * 8 + warp) * GPW + q;   // 0..511
            const int l0 = g * 32;

            // 16 contiguous pixels of this lane's feature row (4x LDG.128)
            const float* ip = inp + ((size_t)b * F + f) * L + l0 + half * 16;
            float4 v0 = *(const float4*)(ip + 0);
            float4 v1 = *(const float4*)(ip + 4);
            float4 v2 = *(const float4*)(ip + 8);
            float4 v3 = *(const float4*)(ip + 12);
            float preg[16] = {v0.x, v0.y, v0.z, v0.w, v1.x, v1.y, v1.z, v1.w,
                              v2.x, v2.y, v2.z, v2.w, v3.x, v3.y, v3.z, v3.w};

            const int* tb = tgt + ((size_t)b * NI + i0) * L + l0 + lane;
            int tval[IH];
#pragma unroll
            for (int j = 0; j < IH; j++)
                tval[j] = (j < ni) ? tb[(size_t)j * L] : 0;

#pragma unroll
            for (int j = 0; j < IH; j++) {
                if (j >= ni) break;               // warp-uniform
                unsigned mi = __ballot_sync(0xffffffffu, tval[j] != 0);
                if (lane == 0) g_masks[b][g][i0 + j] = mi;
                ct[j] += (float)__popc(mi);       // uniform; lane0's copy used
                unsigned sub = (mi >> (half * 16)) & 0xffffu;
                float a0 = 0.f, a1 = 0.f;
#pragma unroll
                for (int k = 0; k < 16; k += 2) {
                    if ((sub >> k) & 1u)       a0 += preg[k];
                    if ((sub >> (k + 1)) & 1u) a1 += preg[k + 1];
                }
                acc[j] += a0 + a1;
            }
        }
    }

    // combine pixel-halves per f, stage to shared
#pragma unroll
    for (int j = 0; j < IH; j++) {
        float a = acc[j];
        a += __shfl_down_sync(0xffffffffu, a, 16);
        if (lane < 16) sh_w[warp][j][f] = a;
        if (lane == 0) sh_c[warp][j] = ct[j];
    }
    __syncthreads();

    // block tree-reduce -> one global atomic per (i,f) per block (52K total chipwide)
    for (int idx = tid; idx < IH * F; idx += 256) {
        int j = idx >> 4, ff = idx & 15;
        if (i0 + j < nb) {
            float s = 0.f;
#pragma unroll
            for (int w = 0; w < 8; w++) s += sh_w[w][j][ff];
            atomicAdd(&g_sumsP[b][i0 + j][ff], s);
        }
    }
    if (tid < IH && i0 + tid < nb) {
        float s = 0.f;
#pragma unroll
        for (int w = 0; w < 8; w++) s += sh_c[w][tid];
        atomicAdd(&g_counts[b][i0 + tid], s);
    }
}

// ================= K2: means / mm / varden / reg / hinge + rezero =================
__global__ void k_stats(const int* __restrict__ nobj_arr) {
    __shared__ float smeans[BS * NI * F];         // 12KB
    __shared__ float sh_h[BS], sh_r[BS], sh_v[BS];
    const int tid = threadIdx.x;
    if (tid < BS) { sh_h[tid] = 0.f; sh_r[tid] = 0.f; sh_v[tid] = 0.f; }

    for (int idx = tid; idx < BS * NI * F; idx += 256) {
        int bb = idx / (NI * F);
        int r  = idx % (NI * F);
        int i  = r >> 4, ff = r & 15;
        float mval = 0.f;
        if (i < nobj_arr[bb]) {
            float c = g_counts[bb][i];
            mval = g_sumsP[bb][i][ff] / (c > 0.f ? c : 1.f);
        }
        smeans[idx] = mval;
        ((float*)g_means)[idx] = mval;
    }
    __syncthreads();

    for (int idx = tid; idx < BS * NI; idx += 256) {
        int bb = idx / NI, i = idx % NI;
        float mm = 0.f;
#pragma unroll
        for (int ff = 0; ff < F; ff++) {
            float m = smeans[idx * F + ff];
            mm += m * m;
        }
        g_mm[bb][i] = mm;
        if (i < nobj_arr[bb]) {
            atomicAdd(&sh_v[bb], g_counts[bb][i]);
            atomicAdd(&sh_r[bb], mm > 0.f ? sqrtf(mm) : 0.f);
        }
    }
    for (int idx = tid; idx < BS * NI * NI; idx += 256) {
        int bb = idx / (NI * NI);
        int r  = idx % (NI * NI);
        int i = r / NI, j = r % NI;
        int nbb = nobj_arr[bb];
        if (i < nbb && j < nbb && i != j) {
            float ss = 0.f;
#pragma unroll
            for (int ff = 0; ff < F; ff++) {
                float d = smeans[(bb * NI + i) * F + ff] - smeans[(bb * NI + j) * F + ff];
                ss += d * d;
            }
            float dn = ss > 0.f ? sqrtf(ss) : 0.f;
            float h = fmaxf(3.0f - dn, 0.f);      // margin = 2*delta_d
            atomicAdd(&sh_h[bb], h * h);
        }
    }
    __syncthreads();
    if (tid < BS) {
        g_varden[tid] = sh_v[tid];
        g_hinge[tid]  = sh_h[tid];
        g_reg[tid]    = sh_r[tid];
    }
    // rezero for next replay
    for (int idx = tid; idx < BS * NI * 32; idx += 256) ((float*)g_sumsP)[idx] = 0.f;
    for (int idx = tid; idx < BS * NI; idx += 256)      ((float*)g_counts)[idx] = 0.f;
}

// ================= K3: var_num — pixel-pair threads, full f32x2 =================
// grid = (64, BS): blockIdx.x = pairblk*2 + ih. Warp covers 64 px (2 groups).
__global__ void __launch_bounds__(256) k_var(const float* __restrict__ inp,
                                             const int* __restrict__ nobj) {
    const int b       = blockIdx.y;
    const int ih      = blockIdx.x & 1;
    const int pairblk = blockIdx.x >> 1;          // 0..31
    const int tid  = threadIdx.x;
    const int lane = tid & 31;
    const int warp = tid >> 5;
    const int i0   = ih * IH;
    const int w0   = (pairblk * 8 + warp) * 64;   // warp's first pixel
    const int px0  = w0 + 2 * lane;
    const int grp0 = w0 >> 5;
    const int nb   = __ldg(nobj + b);
    int ni = nb - i0; ni = ni < 0 ? 0 : (ni > IH ? IH : ni);

    __shared__ unsigned long long m2[NI * F];     // (m,m) pairs, 3KB
    __shared__ unsigned long long smm[NI];        // (mm,mm) pairs
    __shared__ float red[8];

    for (int idx = tid; idx < NI * F; idx += 256) {
        float m = ((const float*)g_means)[b * NI * F + idx];
        unsigned long long d;
        asm("mov.b64 %0,{%1,%2};" : "=l"(d) : "f"(m), "f"(m));
        m2[idx] = d;
    }
    if (tid < NI) {
        float v = g_mm[b][tid];
        unsigned long long d;
        asm("mov.b64 %0,{%1,%2};" : "=l"(d) : "f"(v), "f"(v));
        smm[tid] = d;
    }
    __syncthreads();

    float local = 0.f;
    if (ni > 0) {
        // 2 adjacent pixels, 16 features: 16x LDG.64, coalesced
        const float* ib = inp + (size_t)b * F * L + px0;
        unsigned long long p2[F];
#pragma unroll
        for (int ff = 0; ff < F; ff++) {
            float2 v = *(const float2*)(ib + (size_t)ff * L);
            asm("mov.b64 %0,{%1,%2};" : "=l"(p2[ff]) : "f"(v.x), "f"(v.y));
        }
        // ppPair = (||p0||^2, ||p1||^2)
        unsigned long long qa = 0ull, qb = 0ull;
#pragma unroll
        for (int q = 0; q < 8; q++) {
            asm("fma.rn.f32x2 %0,%1,%2,%3;" : "=l"(qa) : "l"(p2[2*q]),   "l"(p2[2*q]),   "l"(qa));
            asm("fma.rn.f32x2 %0,%1,%2,%3;" : "=l"(qb) : "l"(p2[2*q+1]), "l"(p2[2*q+1]), "l"(qb));
        }
        unsigned long long ppP;
        asm("add.rn.f32x2 %0,%1,%2;" : "=l"(ppP) : "l"(qa), "l"(qb));

        // masks: lanes 0-11 hold grp0's, lanes 16-27 hold grp1's
        const int lh = lane & 15;
        unsigned mw = 0;
        if (lh < IH) mw = g_masks[b][grp0 + (lane >> 4)][i0 + lh];

        const unsigned long long NEG2 = 0xC0000000C0000000ull;  // (-2.f,-2.f)

#pragma unroll
        for (int j = 0; j < IH; j++) {
            if (j >= ni) break;
            unsigned mi = __shfl_sync(0xffffffffu, mw, (lane & 16) + j);
            unsigned bits = (mi >> (2 * (lane & 15))) & 3u;
            if (bits) {
                unsigned long long da = 0ull, db = 0ull;
#pragma unroll
                for (int q = 0; q < 8; q++) {
                    asm("fma.rn.f32x2 %0,%1,%2,%3;" : "=l"(da)
                        : "l"(p2[2*q]),   "l"(m2[(i0+j)*F + 2*q]),   "l"(da));
                    asm("fma.rn.f32x2 %0,%1,%2,%3;" : "=l"(db)
                        : "l"(p2[2*q+1]), "l"(m2[(i0+j)*F + 2*q+1]), "l"(db));
                }
                unsigned long long dotP, base, ssP;
                asm("add.rn.f32x2 %0,%1,%2;" : "=l"(dotP) : "l"(da), "l"(db));
                asm("add.rn.f32x2 %0,%1,%2;" : "=l"(base) : "l"(ppP), "l"(smm[i0+j]));
                asm("fma.rn.f32x2 %0,%1,%2,%3;" : "=l"(ssP) : "l"(NEG2), "l"(dotP), "l"(base));
                float ss0, ss1;
                asm("mov.b64 {%0,%1},%2;" : "=f"(ss0), "=f"(ss1) : "l"(ssP));
                if ((bits & 1u) && ss0 > 0.25f) {
                    float h = sqrtf(ss0) - 0.5f;
                    local += h * h;
                }
                if ((bits & 2u) && ss1 > 0.25f) {
                    float h = sqrtf(ss1) - 0.5f;
                    local += h * h;
                }
            }
        }
    }

#pragma unroll
    for (int o = 16; o > 0; o >>= 1)
        local += __shfl_down_sync(0xffffffffu, local, o);
    if (lane == 0) red[warp] = local;
    __syncthreads();
    if (tid < 8) {
        float v = red[tid];
#pragma unroll
        for (int o = 4; o > 0; o >>= 1)
            v += __shfl_down_sync(0xffu, v, o);
        if (tid == 0) atomicAdd(&g_varnum[b], v);
    }
}

// ================= K4: finalize + rezero =================
__global__ void k_final(const int* __restrict__ nobj_arr, float* __restrict__ out) {
    const int tid = threadIdx.x;
    if (tid == 0) {
        float var_t = 0.f, dist_t = 0.f, reg_t = 0.f;
        for (int b = 0; b < BS; b++) {
            var_t += g_varnum[b] / g_varden[b];
            float nf = (float)nobj_arr[b];
            float denom = nf > 1.f ? nf * (nf - 1.f) : 1.f;
            dist_t += (nf > 1.f) ? g_hinge[b] / denom : 0.f;
            reg_t += g_reg[b] / nf;
        }
        out[0] = var_t / BS + dist_t / BS + 0.001f * (reg_t / BS);
    }
    if (tid < BS) g_varnum[tid] = 0.f;
}

// ---------------- launch ----------------
extern "C" void kernel_launch(void* const* d_in, const int* in_sizes, int n_in,
                              void* d_out, int out_size) {
    const float* inp  = (const float*)d_in[0];   // (8,16,128,128) f32
    const int*   tgt  = (const int*)d_in[1];     // (8,24,128,128) i32
    const int*   nobj = (const int*)d_in[2];     // (8,1) i32
    (void)in_sizes; (void)n_in; (void)out_size;

    dim3 gs(32, BS);                             // 256 blocks
    k_sums<<<gs, 256>>>(inp, tgt, nobj);
    k_stats<<<1, 256>>>(nobj);
    dim3 gv(64, BS);                             // 512 blocks
    k_var<<<gv, 256>>>(inp, nobj);
    k_final<<<1, 32>>>(nobj, (float*)d_out);
}

// round 8
// speedup vs baseline: 1.0602x; 1.0602x over previous
#include <cuda_runtime.h>
#include <math.h>

#define BS 8
#define F 16
#define NI 24
#define L 16384            // H*W
#define NGRP (L / 32)      // 512 pixel-groups per batch
#define IH 12              // instances per warp in k_var
#define GPW 4              // groups per warp in k_sums
#define STPB 128           // k_sums threads per block (4 warps)

// ---------------- scratch (no allocations; zero-init; kernels restore zeros) ----------
__device__ float    g_sumsP[BS][NI][32];   // padded: one 128B line per (b,i)
__device__ float    g_counts[BS][NI];
__device__ float    g_means[BS][NI][F];
__device__ float    g_mm[BS][NI];
__device__ unsigned g_masks[BS][NGRP][NI];
__device__ float    g_varnum[BS];
__device__ float    g_varden[BS];
__device__ float    g_hinge[BS];
__device__ float    g_reg[BS];

// ================= K1: sums / counts / masks (nibble-table accumulate) =============
// grid = (32, BS), 128 threads (4 warps). Warp covers 4 groups x ALL valid instances.
__global__ void __launch_bounds__(STPB) k_sums(const float* __restrict__ inp,
                                               const int* __restrict__ tgt,
                                               const int* __restrict__ nobj) {
    const int b    = blockIdx.y;
    const int blkb = blockIdx.x;                  // 0..31
    const int tid  = threadIdx.x;
    const int warp = tid >> 5;
    const int lane = tid & 31;
    const int f    = lane & 15;
    const int half = lane >> 4;
    const int nb   = __ldg(nobj + b);

    __shared__ float tbl[4 * 16 * STPB];          // 32KB nibble tables, lane-major
    __shared__ float sh_w[4][NI][F];              // 6KB warp partials
    __shared__ float sh_c[4][NI];

    float acc[NI];
#pragma unroll
    for (int j = 0; j < NI; j++) acc[j] = 0.f;
    int mycnt = 0;                                // lane j accumulates count of instance j

    for (int q = 0; q < GPW; q++) {
        const int g  = (blkb * 4 + warp) * GPW + q;   // 0..511
        const int l0 = g * 32;

        // 16 contiguous pixels of this lane's feature row (4x LDG.128)
        const float* ip = inp + ((size_t)b * F + f) * L + l0 + half * 16;
        float4 v0 = *(const float4*)(ip + 0);
        float4 v1 = *(const float4*)(ip + 4);
        float4 v2 = *(const float4*)(ip + 8);
        float4 v3 = *(const float4*)(ip + 12);
        float p[16] = {v0.x, v0.y, v0.z, v0.w, v1.x, v1.y, v1.z, v1.w,
                       v2.x, v2.y, v2.z, v2.w, v3.x, v3.y, v3.z, v3.w};

        // ---- build 4 nibble subset-sum tables (private column, no sync needed) ----
#pragma unroll
        for (int n = 0; n < 4; n++) {
            float a0 = p[4*n], a1 = p[4*n+1], a2 = p[4*n+2], a3 = p[4*n+3];
            float s01 = a0+a1, s02 = a0+a2, s12 = a1+a2;
            float s03 = a0+a3, s13 = a1+a3, s23 = a2+a3;
            float s012 = s01+a2, s013 = s01+a3, s023 = s02+a3, s123 = s12+a3;
            float s0123 = s012+a3;
            float* T = &tbl[(n * 16) * STPB + tid];
            T[ 0*STPB] = 0.f;  T[ 1*STPB] = a0;   T[ 2*STPB] = a1;   T[ 3*STPB] = s01;
            T[ 4*STPB] = a2;   T[ 5*STPB] = s02;  T[ 6*STPB] = s12;  T[ 7*STPB] = s012;
            T[ 8*STPB] = a3;   T[ 9*STPB] = s03;  T[10*STPB] = s13;  T[11*STPB] = s013;
            T[12*STPB] = s23;  T[13*STPB] = s023; T[14*STPB] = s123; T[15*STPB] = s0123;
        }

        // ---- batched target loads (lane = pixel), valid instances only ----
        const int* tb = tgt + ((size_t)b * NI) * L + l0 + lane;
        int tval[NI];
#pragma unroll
        for (int j = 0; j < NI; j++)
            tval[j] = (j < nb) ? tb[(size_t)j * L] : 0;

        // ---- per-instance: ballot -> 4 table lookups ----
#pragma unroll
        for (int j = 0; j < NI; j++) {
            if (j >= nb) break;                   // nb warp-uniform
            unsigned mi = __ballot_sync(0xffffffffu, tval[j] != 0);
            if (lane == j) g_masks[b][g][j] = mi;
            mycnt += (lane == j) ? __popc(mi) : 0;
            unsigned sub = (mi >> (half * 16)) & 0xffffu;
            float t0 = tbl[(0*16 + ( sub        & 15u)) * STPB + tid];
            float t1 = tbl[(1*16 + ((sub >>  4) & 15u)) * STPB + tid];
            float t2 = tbl[(2*16 + ((sub >>  8) & 15u)) * STPB + tid];
            float t3 = tbl[(3*16 + ( sub >> 12       )) * STPB + tid];
            acc[j] += (t0 + t1) + (t2 + t3);
        }
    }

    // combine pixel-halves per f, stage to shared
#pragma unroll
    for (int j = 0; j < NI; j++) {
        float a = acc[j];
        a += __shfl_down_sync(0xffffffffu, a, 16);
        if (lane < 16) sh_w[warp][j][f] = a;
    }
    if (lane < NI) sh_c[warp][lane] = (float)mycnt;
    __syncthreads();

    // block tree-reduce -> one global atomic per (i,f)
    for (int idx = tid; idx < NI * F; idx += STPB) {
        int j = idx >> 4, ff = idx & 15;
        if (j < nb) {
            float s = 0.f;
#pragma unroll
            for (int w = 0; w < 4; w++) s += sh_w[w][j][ff];
            atomicAdd(&g_sumsP[b][j][ff], s);
        }
    }
    if (tid < NI && tid < nb) {
        float s = 0.f;
#pragma unroll
        for (int w = 0; w < 4; w++) s += sh_c[w][tid];
        atomicAdd(&g_counts[b][tid], s);
    }
}

// ================= K2: means / mm / varden / reg / hinge + rezero =================
__global__ void k_stats(const int* __restrict__ nobj_arr) {
    __shared__ float smeans[BS * NI * F];         // 12KB
    __shared__ float sh_h[BS], sh_r[BS], sh_v[BS];
    const int tid = threadIdx.x;
    if (tid < BS) { sh_h[tid] = 0.f; sh_r[tid] = 0.f; sh_v[tid] = 0.f; }

    for (int idx = tid; idx < BS * NI * F; idx += 256) {
        int bb = idx / (NI * F);
        int r  = idx % (NI * F);
        int i  = r >> 4, ff = r & 15;
        float mval = 0.f;
        if (i < nobj_arr[bb]) {
            float c = g_counts[bb][i];
            mval = g_sumsP[bb][i][ff] / (c > 0.f ? c : 1.f);
        }
        smeans[idx] = mval;
        ((float*)g_means)[idx] = mval;
    }
    __syncthreads();

    for (int idx = tid; idx < BS * NI; idx += 256) {
        int bb = idx / NI, i = idx % NI;
        float mm = 0.f;
#pragma unroll
        for (int ff = 0; ff < F; ff++) {
            float m = smeans[idx * F + ff];
            mm += m * m;
        }
        g_mm[bb][i] = mm;
        if (i < nobj_arr[bb]) {
            atomicAdd(&sh_v[bb], g_counts[bb][i]);
            atomicAdd(&sh_r[bb], mm > 0.f ? sqrtf(mm) : 0.f);
        }
    }
    for (int idx = tid; idx < BS * NI * NI; idx += 256) {
        int bb = idx / (NI * NI);
        int r  = idx % (NI * NI);
        int i = r / NI, j = r % NI;
        int nbb = nobj_arr[bb];
        if (i < nbb && j < nbb && i != j) {
            float ss = 0.f;
#pragma unroll
            for (int ff = 0; ff < F; ff++) {
                float d = smeans[(bb * NI + i) * F + ff] - smeans[(bb * NI + j) * F + ff];
                ss += d * d;
            }
            float dn = ss > 0.f ? sqrtf(ss) : 0.f;
            float h = fmaxf(3.0f - dn, 0.f);      // margin = 2*delta_d
            atomicAdd(&sh_h[bb], h * h);
        }
    }
    __syncthreads();
    if (tid < BS) {
        g_varden[tid] = sh_v[tid];
        g_hinge[tid]  = sh_h[tid];
        g_reg[tid]    = sh_r[tid];
    }
    // rezero for next replay
    for (int idx = tid; idx < BS * NI * 32; idx += 256) ((float*)g_sumsP)[idx] = 0.f;
    for (int idx = tid; idx < BS * NI; idx += 256)      ((float*)g_counts)[idx] = 0.f;
}

// ================= K3: var_num — pixel-pair threads, full f32x2 =================
// grid = (64, BS): blockIdx.x = pairblk*2 + ih. Warp covers 64 px (2 groups).
__global__ void __launch_bounds__(256) k_var(const float* __restrict__ inp,
                                             const int* __restrict__ nobj) {
    const int b       = blockIdx.y;
    const int ih      = blockIdx.x & 1;
    const int pairblk = blockIdx.x >> 1;          // 0..31
    const int tid  = threadIdx.x;
    const int lane = tid & 31;
    const int warp = tid >> 5;
    const int i0   = ih * IH;
    const int w0   = (pairblk * 8 + warp) * 64;   // warp's first pixel
    const int px0  = w0 + 2 * lane;
    const int grp0 = w0 >> 5;
    const int nb   = __ldg(nobj + b);
    int ni = nb - i0; ni = ni < 0 ? 0 : (ni > IH ? IH : ni);

    __shared__ unsigned long long m2[NI * F];     // (m,m) pairs, 3KB
    __shared__ unsigned long long smm[NI];        // (mm,mm) pairs
    __shared__ float red[8];

    for (int idx = tid; idx < NI * F; idx += 256) {
        float m = ((const float*)g_means)[b * NI * F + idx];
        unsigned long long d;
        asm("mov.b64 %0,{%1,%2};" : "=l"(d) : "f"(m), "f"(m));
        m2[idx] = d;
    }
    if (tid < NI) {
        float v = g_mm[b][tid];
        unsigned long long d;
        asm("mov.b64 %0,{%1,%2};" : "=l"(d) : "f"(v), "f"(v));
        smm[tid] = d;
    }
    __syncthreads();

    float local = 0.f;
    if (ni > 0) {
        // 2 adjacent pixels, 16 features: 16x LDG.64, coalesced
        const float* ib = inp + (size_t)b * F * L + px0;
        unsigned long long p2[F];
#pragma unroll
        for (int ff = 0; ff < F; ff++) {
            float2 v = *(const float2*)(ib + (size_t)ff * L);
            asm("mov.b64 %0,{%1,%2};" : "=l"(p2[ff]) : "f"(v.x), "f"(v.y));
        }
        // ppPair = (||p0||^2, ||p1||^2)
        unsigned long long qa = 0ull, qb = 0ull;
#pragma unroll
        for (int q = 0; q < 8; q++) {
            asm("fma.rn.f32x2 %0,%1,%2,%3;" : "=l"(qa) : "l"(p2[2*q]),   "l"(p2[2*q]),   "l"(qa));
            asm("fma.rn.f32x2 %0,%1,%2,%3;" : "=l"(qb) : "l"(p2[2*q+1]), "l"(p2[2*q+1]), "l"(qb));
        }
        unsigned long long ppP;
        asm("add.rn.f32x2 %0,%1,%2;" : "=l"(ppP) : "l"(qa), "l"(qb));

        // masks: lanes 0-11 hold grp0's, lanes 16-27 hold grp1's
        const int lh = lane & 15;
        unsigned mw = 0;
        if (lh < IH) mw = g_masks[b][grp0 + (lane >> 4)][i0 + lh];

        const unsigned long long NEG2 = 0xC0000000C0000000ull;  // (-2.f,-2.f)

#pragma unroll
        for (int j = 0; j < IH; j++) {
            if (j >= ni) break;
            unsigned mi = __shfl_sync(0xffffffffu, mw, (lane & 16) + j);
            unsigned bits = (mi >> (2 * (lane & 15))) & 3u;
            if (bits) {
                unsigned long long da = 0ull, db = 0ull;
#pragma unroll
                for (int q = 0; q < 8; q++) {
                    asm("fma.rn.f32x2 %0,%1,%2,%3;" : "=l"(da)
                        : "l"(p2[2*q]),   "l"(m2[(i0+j)*F + 2*q]),   "l"(da));
                    asm("fma.rn.f32x2 %0,%1,%2,%3;" : "=l"(db)
                        : "l"(p2[2*q+1]), "l"(m2[(i0+j)*F + 2*q+1]), "l"(db));
                }
                unsigned long long dotP, base, ssP;
                asm("add.rn.f32x2 %0,%1,%2;" : "=l"(dotP) : "l"(da), "l"(db));
                asm("add.rn.f32x2 %0,%1,%2;" : "=l"(base) : "l"(ppP), "l"(smm[i0+j]));
                asm("fma.rn.f32x2 %0,%1,%2,%3;" : "=l"(ssP) : "l"(NEG2), "l"(dotP), "l"(base));
                float ss0, ss1;
                asm("mov.b64 {%0,%1},%2;" : "=f"(ss0), "=f"(ss1) : "l"(ssP));
                if ((bits & 1u) && ss0 > 0.25f) {
                    float h = sqrtf(ss0) - 0.5f;
                    local += h * h;
                }
                if ((bits & 2u) && ss1 > 0.25f) {
                    float h = sqrtf(ss1) - 0.5f;
                    local += h * h;
                }
            }
        }
    }

#pragma unroll
    for (int o = 16; o > 0; o >>= 1)
        local += __shfl_down_sync(0xffffffffu, local, o);
    if (lane == 0) red[warp] = local;
    __syncthreads();
    if (tid < 8) {
        float v = red[tid];
#pragma unroll
        for (int o = 4; o > 0; o >>= 1)
            v += __shfl_down_sync(0xffu, v, o);
        if (tid == 0) atomicAdd(&g_varnum[b], v);
    }
}

// ================= K4: finalize (parallel over batches) + rezero =================
__global__ void k_final(const int* __restrict__ nobj_arr, float* __restrict__ out) {
    const int lane = threadIdx.x;
    float var_t = 0.f, dist_t = 0.f, reg_t = 0.f;
    if (lane < BS) {
        float vd = g_varden[lane];
        var_t = g_varnum[lane] / vd;
        float nf = (float)nobj_arr[lane];
        float denom = nf > 1.f ? nf * (nf - 1.f) : 1.f;
        dist_t = (nf > 1.f) ? g_hinge[lane] / denom : 0.f;
        reg_t = g_reg[lane] / nf;
    }
#pragma unroll
    for (int o = 4; o > 0; o >>= 1) {
        var_t  += __shfl_down_sync(0xffffffffu, var_t,  o);
        dist_t += __shfl_down_sync(0xffffffffu, dist_t, o);
        reg_t  += __shfl_down_sync(0xffffffffu, reg_t,  o);
    }
    if (lane == 0)
        out[0] = var_t / BS + dist_t / BS + 0.001f * (reg_t / BS);
    if (lane < BS) g_varnum[lane] = 0.f;
}

// ---------------- launch ----------------
extern "C" void kernel_launch(void* const* d_in, const int* in_sizes, int n_in,
                              void* d_out, int out_size) {
    const float* inp  = (const float*)d_in[0];   // (8,16,128,128) f32
    const int*   tgt  = (const int*)d_in[1];     // (8,24,128,128) i32
    const int*   nobj = (const int*)d_in[2];     // (8,1) i32
    (void)in_sizes; (void)n_in; (void)out_size;

    dim3 gs(32, BS);                             // 256 blocks x 128 thr
    k_sums<<<gs, STPB>>>(inp, tgt, nobj);
    k_stats<<<1, 256>>>(nobj);
    dim3 gv(64, BS);                             // 512 blocks x 256 thr
    k_var<<<gv, 256>>>(inp, nobj);
    k_final<<<1, 32>>>(nobj, (float*)d_out);
}

// round 9
// speedup vs baseline: 1.3900x; 1.3112x over previous
#include <cuda_runtime.h>
#include <math.h>

#define BS 8
#define F 16
#define NI 24
#define L 16384            // H*W
#define NGRP (L / 32)      // 512 groups of 32 px per batch
#define IH 12              // instances per warp in k_var

// ---------------- scratch (no allocations; zero-init; kernels restore zeros) ----------
__device__ float    g_sumsP[BS][NI][32];   // padded: one 128B line per (b,i)
__device__ float    g_counts[BS][NI];
__device__ float    g_means[BS][NI][F];
__device__ float    g_mm[BS][NI];
__device__ unsigned g_masks[BS][NGRP][NI];
__device__ float    g_varnum[BS];
__device__ float    g_varden[BS];
__device__ float    g_hinge[BS];
__device__ float    g_reg[BS];

// ================= K0: masks + counts from target (int4 reads, no ballots) ==========
// warp = (b, i, 512-px segment). 6144 warps -> 768 blocks x 256.
__global__ void __launch_bounds__(256) k_masks(const int* __restrict__ tgt,
                                               const int* __restrict__ nobj) {
    const int gw   = blockIdx.x * 8 + (threadIdx.x >> 5); // global warp 0..6143
    const int lane = threadIdx.x & 31;
    const int seg  = gw & 31;                  // 512-px segment within row
    const int i    = (gw >> 5) % NI;
    const int b    = gw / (32 * NI);
    if (i >= __ldg(nobj + b)) return;

    const int4* row = (const int4*)(tgt + ((size_t)b * NI + i) * L) + seg * 128 + lane;
    int cnt = 0;

#pragma unroll
    for (int c = 0; c < 4; c++) {              // 4 chunks of 128 px
        int4 t = row[c * 32];
        unsigned nib = (t.x != 0 ? 1u : 0u) | (t.y != 0 ? 2u : 0u)
                     | (t.z != 0 ? 4u : 0u) | (t.w != 0 ? 8u : 0u);
        unsigned w = nib << (4 * (lane & 7));
        // OR-combine within each 8-lane segment (pixels 32g..32g+31)
        w |= __shfl_xor_sync(0xffffffffu, w, 1);
        w |= __shfl_xor_sync(0xffffffffu, w, 2);
        w |= __shfl_xor_sync(0xffffffffu, w, 4);
        if ((lane & 7) == 0) {
            const int grp = seg * 16 + c * 4 + (lane >> 3);
            g_masks[b][grp][i] = w;
            cnt += __popc(w);
        }
    }
    // reduce leaders' counts -> one atomic per warp
#pragma unroll
    for (int o = 16; o > 0; o >>= 1)
        cnt += __shfl_down_sync(0xffffffffu, cnt, o);
    if (lane == 0) atomicAdd(&g_counts[b][i], (float)cnt);
}

// ================= K1: sums (mask-driven, nibble tables; no target reads) ===========
// grid = (32, BS), 256 thr (8 warps), 2 groups per warp.
__global__ void __launch_bounds__(256) k_sums(const float* __restrict__ inp,
                                              const int* __restrict__ nobj) {
    const int b    = blockIdx.y;
    const int tid  = threadIdx.x;
    const int warp = tid >> 5;
    const int lane = tid & 31;
    const int f    = lane & 15;
    const int half = lane >> 4;
    const int nb   = __ldg(nobj + b);

    __shared__ float tbl[4 * 16 * 256];        // 16KB nibble tables, lane-major
    __shared__ float sh_w[8][NI][F];           // 12KB warp partials
    __shared__ float sh_pad[8][8];             // avoid sh_w line aliasing on flush
    (void)sh_pad;

    float acc[NI];
#pragma unroll
    for (int j = 0; j < NI; j++) acc[j] = 0.f;

#pragma unroll
    for (int q = 0; q < 2; q++) {
        const int g  = (blockIdx.x * 8 + warp) * 2 + q;   // 0..511
        const int l0 = g * 32;

        // 16 contiguous pixels of this lane's feature row
        const float* ip = inp + ((size_t)b * F + f) * L + l0 + half * 16;
        float4 v0 = *(const float4*)(ip + 0);
        float4 v1 = *(const float4*)(ip + 4);
        float4 v2 = *(const float4*)(ip + 8);
        float4 v3 = *(const float4*)(ip + 12);
        float p[16] = {v0.x, v0.y, v0.z, v0.w, v1.x, v1.y, v1.z, v1.w,
                       v2.x, v2.y, v2.z, v2.w, v3.x, v3.y, v3.z, v3.w};

        // this group's mask row: coalesced 96B load across lanes 0..23
        unsigned mrow = (lane < NI) ? g_masks[b][g][lane] : 0u;

        // build 4 nibble subset-sum tables (private column per tid)
#pragma unroll
        for (int n = 0; n < 4; n++) {
            float a0 = p[4*n], a1 = p[4*n+1], a2 = p[4*n+2], a3 = p[4*n+3];
            float s01 = a0+a1, s02 = a0+a2, s12 = a1+a2;
            float s03 = a0+a3, s13 = a1+a3, s23 = a2+a3;
            float s012 = s01+a2, s013 = s01+a3, s023 = s02+a3, s123 = s12+a3;
            float s0123 = s012+a3;
            float* T = &tbl[(n * 16) * 256 + tid];
            T[ 0*256] = 0.f;  T[ 1*256] = a0;   T[ 2*256] = a1;   T[ 3*256] = s01;
            T[ 4*256] = a2;   T[ 5*256] = s02;  T[ 6*256] = s12;  T[ 7*256] = s012;
            T[ 8*256] = a3;   T[ 9*256] = s03;  T[10*256] = s13;  T[11*256] = s013;
            T[12*256] = s23;  T[13*256] = s023; T[14*256] = s123; T[15*256] = s0123;
        }

#pragma unroll
        for (int j = 0; j < NI; j++) {
            if (j >= nb) break;                // warp-uniform
            unsigned mi  = __shfl_sync(0xffffffffu, mrow, j);
            unsigned sub = (mi >> (half * 16)) & 0xffffu;
            float t0 = tbl[(0*16 + ( sub        & 15u)) * 256 + tid];
            float t1 = tbl[(1*16 + ((sub >>  4) & 15u)) * 256 + tid];
            float t2 = tbl[(2*16 + ((sub >>  8) & 15u)) * 256 + tid];
            float t3 = tbl[(3*16 + ( sub >> 12       )) * 256 + tid];
            acc[j] += (t0 + t1) + (t2 + t3);
        }
    }

    // combine pixel-halves per f, stage to shared
#pragma unroll
    for (int j = 0; j < NI; j++) {
        float a = acc[j];
        a += __shfl_down_sync(0xffffffffu, a, 16);
        if (lane < 16) sh_w[warp][j][f] = a;
    }
    __syncthreads();

    // block tree-reduce -> one global atomic per (i,f)
    for (int idx = tid; idx < NI * F; idx += 256) {
        int j = idx >> 4, ff = idx & 15;
        if (j < nb) {
            float s = 0.f;
#pragma unroll
            for (int w = 0; w < 8; w++) s += sh_w[w][j][ff];
            atomicAdd(&g_sumsP[b][j][ff], s);
        }
    }
}

// ================= K2: means / mm / varden / reg / hinge + rezero ===================
// 768 threads: batched independent loads (high MLP, short dependent chains).
__global__ void __launch_bounds__(768) k_stats(const int* __restrict__ nobj_arr) {
    __shared__ float smeans[BS * NI * F];      // 12KB
    __shared__ float sh_h[BS], sh_r[BS], sh_v[BS];
    const int tid = threadIdx.x;
    if (tid < BS) { sh_h[tid] = 0.f; sh_r[tid] = 0.f; sh_v[tid] = 0.f; }

    // means: 3072 elems over 768 threads = 4 independent rounds
    float mv[4]; int bi[4];
#pragma unroll
    for (int r = 0; r < 4; r++) {
        int idx = tid + r * 768;
        int bb = idx / (NI * F);
        int rr = idx % (NI * F);
        int i  = rr >> 4, ff = rr & 15;
        bi[r] = idx;
        float mval = 0.f;
        if (i < nobj_arr[bb]) {
            float c = g_counts[bb][i];
            mval = g_sumsP[bb][i][ff] / (c > 0.f ? c : 1.f);
        }
        mv[r] = mval;
    }
#pragma unroll
    for (int r = 0; r < 4; r++) {
        smeans[bi[r]] = mv[r];
        ((float*)g_means)[bi[r]] = mv[r];
    }
    __syncthreads();

    if (tid < BS * NI) {
        int bb = tid / NI, i = tid % NI;
        float mm = 0.f;
#pragma unroll
        for (int ff = 0; ff < F; ff++) {
            float m = smeans[tid * F + ff];
            mm += m * m;
        }
        g_mm[bb][i] = mm;
        if (i < nobj_arr[bb]) {
            atomicAdd(&sh_v[bb], g_counts[bb][i]);
            atomicAdd(&sh_r[bb], mm > 0.f ? sqrtf(mm) : 0.f);
        }
    }
    // pairwise hinge: 4608 pairs over 768 threads = 6 rounds, shared-only math
    for (int idx = tid; idx < BS * NI * NI; idx += 768) {
        int bb = idx / (NI * NI);
        int r  = idx % (NI * NI);
        int i = r / NI, j = r % NI;
        int nbb = nobj_arr[bb];
        if (i < nbb && j < nbb && i != j) {
            float ss = 0.f;
#pragma unroll
            for (int ff = 0; ff < F; ff++) {
                float d = smeans[(bb * NI + i) * F + ff] - smeans[(bb * NI + j) * F + ff];
                ss += d * d;
            }
            float dn = ss > 0.f ? sqrtf(ss) : 0.f;
            float h = fmaxf(3.0f - dn, 0.f);   // margin = 2*delta_d
            atomicAdd(&sh_h[bb], h * h);
        }
    }
    __syncthreads();
    if (tid < BS) {
        g_varden[tid] = sh_v[tid];
        g_hinge[tid]  = sh_h[tid];
        g_reg[tid]    = sh_r[tid];
    }
    // rezero for next replay
    for (int idx = tid; idx < BS * NI * 32; idx += 768) ((float*)g_sumsP)[idx] = 0.f;
    if (tid < BS * NI) ((float*)g_counts)[tid] = 0.f;
}

// ================= K3: var_num — pixel-pair threads, full f32x2 =====================
__global__ void __launch_bounds__(256) k_var(const float* __restrict__ inp,
                                             const int* __restrict__ nobj) {
    const int b       = blockIdx.y;
    const int ih      = blockIdx.x & 1;
    const int pairblk = blockIdx.x >> 1;       // 0..31
    const int tid  = threadIdx.x;
    const int lane = tid & 31;
    const int warp = tid >> 5;
    const int i0   = ih * IH;
    const int w0   = (pairblk * 8 + warp) * 64;
    const int px0  = w0 + 2 * lane;
    const int grp0 = w0 >> 5;
    const int nb   = __ldg(nobj + b);
    int ni = nb - i0; ni = ni < 0 ? 0 : (ni > IH ? IH : ni);

    __shared__ unsigned long long m2[NI * F];  // (m,m) pairs
    __shared__ unsigned long long smm[NI];     // (mm,mm) pairs
    __shared__ float red[8];

    for (int idx = tid; idx < NI * F; idx += 256) {
        float m = ((const float*)g_means)[b * NI * F + idx];
        unsigned long long d;
        asm("mov.b64 %0,{%1,%2};" : "=l"(d) : "f"(m), "f"(m));
        m2[idx] = d;
    }
    if (tid < NI) {
        float v = g_mm[b][tid];
        unsigned long long d;
        asm("mov.b64 %0,{%1,%2};" : "=l"(d) : "f"(v), "f"(v));
        smm[tid] = d;
    }
    __syncthreads();

    float local = 0.f;
    if (ni > 0) {
        const float* ib = inp + (size_t)b * F * L + px0;
        unsigned long long p2[F];
#pragma unroll
        for (int ff = 0; ff < F; ff++) {
            float2 v = *(const float2*)(ib + (size_t)ff * L);
            asm("mov.b64 %0,{%1,%2};" : "=l"(p2[ff]) : "f"(v.x), "f"(v.y));
        }
        unsigned long long qa = 0ull, qb = 0ull;
#pragma unroll
        for (int q = 0; q < 8; q++) {
            asm("fma.rn.f32x2 %0,%1,%2,%3;" : "=l"(qa) : "l"(p2[2*q]),   "l"(p2[2*q]),   "l"(qa));
            asm("fma.rn.f32x2 %0,%1,%2,%3;" : "=l"(qb) : "l"(p2[2*q+1]), "l"(p2[2*q+1]), "l"(qb));
        }
        unsigned long long ppP;
        asm("add.rn.f32x2 %0,%1,%2;" : "=l"(ppP) : "l"(qa), "l"(qb));

        const int lh = lane & 15;
        unsigned mw = 0;
        if (lh < IH) mw = g_masks[b][grp0 + (lane >> 4)][i0 + lh];

        const unsigned long long NEG2 = 0xC0000000C0000000ull;   // (-2.f,-2.f)

#pragma unroll
        for (int j = 0; j < IH; j++) {
            if (j >= ni) break;
            unsigned mi = __shfl_sync(0xffffffffu, mw, (lane & 16) + j);
            unsigned bits = (mi >> (2 * (lane & 15))) & 3u;
            if (bits) {
                unsigned long long da = 0ull, db = 0ull;
#pragma unroll
                for (int q = 0; q < 8; q++) {
                    asm("fma.rn.f32x2 %0,%1,%2,%3;" : "=l"(da)
                        : "l"(p2[2*q]),   "l"(m2[(i0+j)*F + 2*q]),   "l"(da));
                    asm("fma.rn.f32x2 %0,%1,%2,%3;" : "=l"(db)
                        : "l"(p2[2*q+1]), "l"(m2[(i0+j)*F + 2*q+1]), "l"(db));
                }
                unsigned long long dotP, base, ssP;
                asm("add.rn.f32x2 %0,%1,%2;" : "=l"(dotP) : "l"(da), "l"(db));
                asm("add.rn.f32x2 %0,%1,%2;" : "=l"(base) : "l"(ppP), "l"(smm[i0+j]));
                asm("fma.rn.f32x2 %0,%1,%2,%3;" : "=l"(ssP) : "l"(NEG2), "l"(dotP), "l"(base));
                float ss0, ss1;
                asm("mov.b64 {%0,%1},%2;" : "=f"(ss0), "=f"(ss1) : "l"(ssP));
                if ((bits & 1u) && ss0 > 0.25f) {
                    float h = sqrtf(ss0) - 0.5f;
                    local += h * h;
                }
                if ((bits & 2u) && ss1 > 0.25f) {
                    float h = sqrtf(ss1) - 0.5f;
                    local += h * h;
                }
            }
        }
    }

#pragma unroll
    for (int o = 16; o > 0; o >>= 1)
        local += __shfl_down_sync(0xffffffffu, local, o);
    if (lane == 0) red[warp] = local;
    __syncthreads();
    if (tid < 8) {
        float v = red[tid];
#pragma unroll
        for (int o = 4; o > 0; o >>= 1)
            v += __shfl_down_sync(0xffu, v, o);
        if (tid == 0) atomicAdd(&g_varnum[b], v);
    }
}

// ================= K4: finalize (parallel over batches) + rezero ====================
__global__ void k_final(const int* __restrict__ nobj_arr, float* __restrict__ out) {
    const int lane = threadIdx.x;
    float var_t = 0.f, dist_t = 0.f, reg_t = 0.f;
    if (lane < BS) {
        float vd = g_varden[lane];
        var_t = g_varnum[lane] / vd;
        float nf = (float)nobj_arr[lane];
        float denom = nf > 1.f ? nf * (nf - 1.f) : 1.f;
        dist_t = (nf > 1.f) ? g_hinge[lane] / denom : 0.f;
        reg_t = g_reg[lane] / nf;
    }
#pragma unroll
    for (int o = 4; o > 0; o >>= 1) {
        var_t  += __shfl_down_sync(0xffffffffu, var_t,  o);
        dist_t += __shfl_down_sync(0xffffffffu, dist_t, o);
        reg_t  += __shfl_down_sync(0xffffffffu, reg_t,  o);
    }
    if (lane == 0)
        out[0] = var_t / BS + dist_t / BS + 0.001f * (reg_t / BS);
    if (lane < BS) g_varnum[lane] = 0.f;
}

// ---------------- launch ----------------
extern "C" void kernel_launch(void* const* d_in, const int* in_sizes, int n_in,
                              void* d_out, int out_size) {
    const float* inp  = (const float*)d_in[0];   // (8,16,128,128) f32
    const int*   tgt  = (const int*)d_in[1];     // (8,24,128,128) i32
    const int*   nobj = (const int*)d_in[2];     // (8,1) i32
    (void)in_sizes; (void)n_in; (void)out_size;

    k_masks<<<768, 256>>>(tgt, nobj);
    dim3 gs(32, BS);                             // 256 blocks
    k_sums<<<gs, 256>>>(inp, nobj);
    k_stats<<<1, 768>>>(nobj);
    dim3 gv(64, BS);                             // 512 blocks
    k_var<<<gv, 256>>>(inp, nobj);
    k_final<<<1, 32>>>(nobj, (float*)d_out);
}